// round 6
// baseline (speedup 1.0000x reference)
#include <cuda_runtime.h>
#include <cuda_bf16.h>

// ContrastPreservedChromaEnhancement — pure pointwise op over (16,3,1024,1024) fp32.
// HBM-bound: 192 MiB in + 192 MiB out. Strategy: float4-vectorized streaming
// kernel, one thread = 4 pixels x 3 channels. HUE_PARAMS table is symmetric
// (rows 0==5, 1==4, 2==3), so the hue-indexed gather reduces to closed-form
// FMAs on k = min(idx, 5-idx): a1=a3=0.5-0.1k, a2=1.2-0.1k, a4=0.1,
// a5=0.8+0.1*[k==2]. cw=1.2 fixed => term3 = 0.1*(0.44 + 2.2*a5).

#define HW   (1024 * 1024)
#define HW4  (HW / 4)           // 262144 = 2^18

__device__ __forceinline__ float clamp01(float v) {
    return fminf(fmaxf(v, 0.0f), 1.0f);
}

__device__ __forceinline__ void enhance_px(float r, float g, float b,
                                           float& ro, float& go, float& bo) {
    // RGB -> YCbCr (BT.709 matrix from reference)
    float y  = fmaf(0.2126f, r, fmaf(0.7152f, g, 0.0722f * b));
    float cb = fmaf(-0.1146f, r, fmaf(-0.3854f, g, 0.5f * b));
    float cr = fmaf(0.5f, r, fmaf(-0.4542f, g, -0.0458f * b));

    float cb255 = cb * 255.0f;
    float cr255 = cr * 255.0f;
    float chroma = sqrtf(fmaf(cb255, cb255, cr255 * cr255));

    // hue in [0, 360): degrees(atan2) in [-180,180] -> +360 -> fmod 360 (exact op)
    float deg = atan2f(cr255, cb255) * 57.29577951308232f;
    float hue = fmodf(deg + 360.0f, 360.0f);

    float hs = hue / 60.0f;          // in [0, 6)
    float fl = floorf(hs);
    int   il = (int)fl;
    il = (il > 5) ? 5 : ((il < 0) ? 0 : il);   // fp-edge safety
    int   iu = (il == 5) ? 0 : il + 1;
    float alpha = hs - fl;

    // Symmetric table: k = min(idx, 5-idx) in {0,1,2}
    int kl = (il < 3) ? il : 5 - il;
    int ku = (iu < 3) ? iu : 5 - iu;
    float t  = fmaf(alpha, (float)(ku - kl), (float)kl);  // lerped k
    float a1 = fmaf(-0.1f, t, 0.5f);                      // == a3
    float a2 = fmaf(-0.1f, t, 1.2f);
    float sl = (kl == 2) ? 1.0f : 0.0f;
    float su = (ku == 2) ? 1.0f : 0.0f;
    float s  = fmaf(alpha, su - sl, sl);
    float a5 = fmaf(0.1f, s, 0.8f);

    // term3 = a4 * (cw^2 + a5*cw + a5 - 1), a4=0.1, cw=1.2 -> 0.1*(0.44 + 2.2*a5)
    float t3  = 0.1f * fmaf(2.2f, a5, 0.44f);
    // luma log term: log(y_255/255 + 1e-6) + 0.1  (y_255/255 == y to fp32 noise)
    float llt = logf(y + 1e-6f) + 0.1f;
    float t1  = powf(chroma, a1);
    float t2  = fmaf(a2, llt, a1);     // a2*llt + a3, a3 == a1

    float dy = t1 * t2 * t3;
    float yo = clamp01(fmaf(dy, 1.0f / 255.0f, y));

    // YCbCr -> RGB with chroma boost cw = 1.2
    float cbo = cb * 1.2f;
    float cro = cr * 1.2f;
    ro = clamp01(fmaf(1.5748f, cro, yo));
    go = clamp01(fmaf(-0.1873f, cbo, fmaf(-0.4681f, cro, yo)));
    bo = clamp01(fmaf(1.8556f, cbo, yo));
}

__global__ void __launch_bounds__(256)
cpce_kernel(const float* __restrict__ x, float* __restrict__ out, int nvec) {
    int v = blockIdx.x * blockDim.x + threadIdx.x;
    if (v >= nvec) return;

    int bi = v >> 18;            // batch index (HW4 = 2^18)
    int p  = v & (HW4 - 1);      // vec4 index within the channel plane

    const float4* xin  = reinterpret_cast<const float4*>(x)   + (size_t)bi * 3 * HW4 + p;
    float4*       xout = reinterpret_cast<float4*>(out)       + (size_t)bi * 3 * HW4 + p;

    float4 r4 = xin[0];
    float4 g4 = xin[HW4];
    float4 b4 = xin[2 * HW4];

    float4 ro4, go4, bo4;
    enhance_px(r4.x, g4.x, b4.x, ro4.x, go4.x, bo4.x);
    enhance_px(r4.y, g4.y, b4.y, ro4.y, go4.y, bo4.y);
    enhance_px(r4.z, g4.z, b4.z, ro4.z, go4.z, bo4.z);
    enhance_px(r4.w, g4.w, b4.w, ro4.w, go4.w, bo4.w);

    xout[0]       = ro4;
    xout[HW4]     = go4;
    xout[2 * HW4] = bo4;
}

extern "C" void kernel_launch(void* const* d_in, const int* in_sizes, int n_in,
                              void* d_out, int out_size) {
    const float* x = (const float*)d_in[0];
    float* out = (float*)d_out;

    int total = in_sizes[0];          // 16*3*1024*1024
    int nvec  = total / 12;           // vec4 pixel groups per (batch, plane-triple)

    int threads = 256;
    int blocks  = (nvec + threads - 1) / threads;   // 16384
    cpce_kernel<<<blocks, threads>>>(x, out, nvec);
}

// round 8
// speedup vs baseline: 2.0700x; 2.0700x over previous
#include <cuda_runtime.h>
#include <cuda_bf16.h>

// ContrastPreservedChromaEnhancement — pointwise over (16,3,1024,1024) fp32.
// HBM floor ~53us; previous kernel (131us) was ISSUE-bound on accurate libm.
// This version: closed-form triangle functions replace the hue-index lerp,
// polynomial atan2, __powf/__logf MUFU paths, saturate-folded clamps.
//
//   t(hs) = max(0, min(hs, 5-hs, 2))       == lerped k = min(idx,5-idx)
//   s(hs) = sat(min(hs-1, 4-hs))           == lerped [k==2] indicator
//   a1 = a3 = 0.5-0.1t, a2 = 1.2-0.1t, term3/255 = 8.6275e-4 + 8.6275e-5*s

#define HW4  (1024 * 1024 / 4)   // 262144 = 2^18

__device__ __forceinline__ void enhance_px(float r, float g, float b,
                                           float& ro, float& go, float& bo) {
    // RGB -> YCbCr (BT.709)
    float y  = fmaf(0.2126f, r, fmaf(0.7152f, g, 0.0722f * b));
    float cb = fmaf(-0.1146f, r, fmaf(-0.3854f, g, 0.5f * b));
    float cr = fmaf(0.5f, r, fmaf(-0.4542f, g, -0.0458f * b));

    float c2 = fmaf(cb, cb, cr * cr);        // chroma^2 (unscaled)

    // ---- fast atan2(cr, cb) -> hs = hue/60 in [0,6) ----
    float ax = fabsf(cb), ay = fabsf(cr);
    float mx = fmaxf(ax, ay);
    float mn = fminf(ax, ay);
    float q  = __fdividef(mn, mx + 1e-30f);  // in [0,1]; 0/0 guarded -> 0
    float q2 = q * q;
    float p  = fmaf(q2, -0.0117212f, 0.0526533f);
    p = fmaf(q2, p, -0.1164329f);
    p = fmaf(q2, p,  0.1935435f);
    p = fmaf(q2, p, -0.3326235f);
    p = fmaf(q2, p,  0.9999773f);
    float a = p * q;                          // atan(q), err ~2e-5 rad
    a = (ay > ax) ? (1.57079632679f - a) : a; // octant: swap
    a = (cb < 0.0f) ? (3.14159265359f - a) : a;
    a = (cr < 0.0f) ? -a : a;                 // now atan2 in [-pi, pi]
    float hs = a * 0.95492965855f;            // * 3/pi -> [-3, 3]
    hs = (hs < 0.0f) ? hs + 6.0f : hs;        // wrap -> [0, 6)

    // ---- closed-form interpolated params ----
    float t   = fmaxf(0.0f, fminf(fminf(hs, 5.0f - hs), 2.0f));
    float s   = __saturatef(fminf(hs - 1.0f, 4.0f - hs));
    float a1h = fmaf(-0.05f, t, 0.25f);       // a1/2
    float a1  = a1h + a1h;                    // a1 == a3
    float a2  = fmaf(-0.1f, t, 1.2f);
    float t3p = fmaf(8.6274510e-5f, s, 8.6274510e-4f);  // term3/255

    // ---- delta luma ----
    float llt = __logf(y + 1e-6f) + 0.1f;               // log(y255/255+1e-6)+0.1
    float t1  = __powf(c2 * 65025.0f, a1h);             // chroma255 ^ a1
    float t2  = fmaf(a2, llt, a1);                      // a2*llt + a3
    float yo  = __saturatef(fmaf(t1 * t2, t3p, y));

    // ---- YCbCr -> RGB, chroma * 1.2 ----
    float cbo = cb * 1.2f;
    float cro = cr * 1.2f;
    ro = __saturatef(fmaf(1.5748f, cro, yo));
    go = __saturatef(fmaf(-0.1873f, cbo, fmaf(-0.4681f, cro, yo)));
    bo = __saturatef(fmaf(1.8556f, cbo, yo));
}

__global__ void __launch_bounds__(256)
cpce_kernel(const float* __restrict__ x, float* __restrict__ out, int nvec) {
    int v = blockIdx.x * blockDim.x + threadIdx.x;
    if (v >= nvec) return;

    int bi = v >> 18;            // batch index (HW4 = 2^18)
    int pp = v & (HW4 - 1);      // vec4 index within the plane

    const float4* xin  = reinterpret_cast<const float4*>(x)   + (size_t)bi * 3 * HW4 + pp;
    float4*       xout = reinterpret_cast<float4*>(out)       + (size_t)bi * 3 * HW4 + pp;

    float4 r4 = xin[0];
    float4 g4 = xin[HW4];
    float4 b4 = xin[2 * HW4];

    float4 ro4, go4, bo4;
    enhance_px(r4.x, g4.x, b4.x, ro4.x, go4.x, bo4.x);
    enhance_px(r4.y, g4.y, b4.y, ro4.y, go4.y, bo4.y);
    enhance_px(r4.z, g4.z, b4.z, ro4.z, go4.z, bo4.z);
    enhance_px(r4.w, g4.w, b4.w, ro4.w, go4.w, bo4.w);

    xout[0]       = ro4;
    xout[HW4]     = go4;
    xout[2 * HW4] = bo4;
}

extern "C" void kernel_launch(void* const* d_in, const int* in_sizes, int n_in,
                              void* d_out, int out_size) {
    const float* x = (const float*)d_in[0];
    float* out = (float*)d_out;

    int nvec = in_sizes[0] / 12;                    // 4,194,304 vec4 pixel groups
    int threads = 256;
    int blocks  = (nvec + threads - 1) / threads;   // 16384
    cpce_kernel<<<blocks, threads>>>(x, out, nvec);
}

// round 9
// speedup vs baseline: 2.1235x; 1.0258x over previous
#include <cuda_runtime.h>
#include <cuda_bf16.h>

// ContrastPreservedChromaEnhancement — pointwise over (16,3,1024,1024) fp32.
// R8: 63.6us, DRAM=77%, issue=62.7% (mixed-bound). This round:
//  - 2 vec4 groups/thread, 6 front-batched LDG.128 (MLP 3->6) for latency hiding
//  - __ldcs/__stcs streaming hints (single-touch data)
//  - signed-hue identity kills the wrap: w = hs>=0 ? hs : -1-hs;
//    t = clamp(w,0,2); s = sat(w-1)   (== reference's lerped table values)
//  - degree-7 atan minimax (err ~1e-4 rad, way inside 1e-3 tolerance)

#define HW4  (1024 * 1024 / 4)   // 262144 = 2^18 vec4 groups per plane

__device__ __forceinline__ void enhance_px(float r, float g, float b,
                                           float& ro, float& go, float& bo) {
    // RGB -> YCbCr (BT.709)
    float y  = fmaf(0.2126f, r, fmaf(0.7152f, g, 0.0722f * b));
    float cb = fmaf(-0.1146f, r, fmaf(-0.3854f, g, 0.5f * b));
    float cr = fmaf(0.5f, r, fmaf(-0.4542f, g, -0.0458f * b));

    float c2 = fmaf(cb, cb, cr * cr);        // chroma^2 (unscaled)

    // ---- fast atan2(cr, cb), degree-7 minimax ----
    float ax = fabsf(cb), ay = fabsf(cr);
    float mx = fmaxf(ax, ay);
    float mn = fminf(ax, ay);
    float q  = __fdividef(mn, mx + 1e-30f);  // [0,1]; 0/0 guarded -> 0
    float q2 = q * q;
    float p  = fmaf(q2, -0.0851330f, 0.1801410f);
    p = fmaf(q2, p, -0.3302995f);
    p = fmaf(q2, p,  0.9998660f);
    float a = p * q;                          // atan(q)
    a = (ay > ax) ? (1.57079632679f - a) : a; // octant swap
    a = (cb < 0.0f) ? (3.14159265359f - a) : a;
    a = (cr < 0.0f) ? -a : a;                 // atan2 in [-pi, pi]
    float hs = a * 0.95492965855f;            // hue/60 in [-3, 3]

    // ---- closed-form interpolated params (signed-hue identity) ----
    float w   = (hs >= 0.0f) ? hs : (-1.0f - hs);
    float t   = fmaxf(0.0f, fminf(w, 2.0f));  // lerped k
    float s   = __saturatef(w - 1.0f);        // lerped [k==2]
    float a1h = fmaf(-0.05f, t, 0.25f);       // a1/2
    float a1  = a1h + a1h;                    // a1 == a3
    float a2  = fmaf(-0.1f, t, 1.2f);
    float t3p = fmaf(8.6274510e-5f, s, 8.6274510e-4f);  // term3/255

    // ---- delta luma ----
    float llt = __logf(y + 1e-6f) + 0.1f;     // log(y255/255 + 1e-6) + 0.1
    float t1  = __powf(c2 * 65025.0f, a1h);   // chroma255 ^ a1
    float t2  = fmaf(a2, llt, a1);            // a2*llt + a3
    float yo  = __saturatef(fmaf(t1 * t2, t3p, y));

    // ---- YCbCr -> RGB, chroma * 1.2 ----
    float cbo = cb * 1.2f;
    float cro = cr * 1.2f;
    ro = __saturatef(fmaf(1.5748f, cro, yo));
    go = __saturatef(fmaf(-0.1873f, cbo, fmaf(-0.4681f, cro, yo)));
    bo = __saturatef(fmaf(1.8556f, cbo, yo));
}

__device__ __forceinline__ float4 ld_cs4(const float4* p) { return __ldcs(p); }

__global__ void __launch_bounds__(256)
cpce_kernel(const float* __restrict__ x, float* __restrict__ out) {
    // Block covers 512 consecutive vec4 groups (512 | 2^18, so one plane set).
    int g0 = blockIdx.x * 512 + threadIdx.x;   // first group
    int bi = g0 >> 18;                         // batch index
    int p0 = g0 & (HW4 - 1);                   // vec4 index in plane
    // second group is p0 + 256, same batch (512-aligned chunk)

    const float4* xin  = reinterpret_cast<const float4*>(x)  + (size_t)bi * 3 * HW4 + p0;
    float4*       xout = reinterpret_cast<float4*>(out)      + (size_t)bi * 3 * HW4 + p0;

    // Front-batch all 6 loads (MLP=6)
    float4 rA = ld_cs4(xin);
    float4 rB = ld_cs4(xin + 256);
    float4 gA = ld_cs4(xin + HW4);
    float4 gB = ld_cs4(xin + HW4 + 256);
    float4 bA = ld_cs4(xin + 2 * HW4);
    float4 bB = ld_cs4(xin + 2 * HW4 + 256);

    float4 roA, goA, boA, roB, goB, boB;
    enhance_px(rA.x, gA.x, bA.x, roA.x, goA.x, boA.x);
    enhance_px(rA.y, gA.y, bA.y, roA.y, goA.y, boA.y);
    enhance_px(rA.z, gA.z, bA.z, roA.z, goA.z, boA.z);
    enhance_px(rA.w, gA.w, bA.w, roA.w, goA.w, boA.w);
    enhance_px(rB.x, gB.x, bB.x, roB.x, goB.x, boB.x);
    enhance_px(rB.y, gB.y, bB.y, roB.y, goB.y, boB.y);
    enhance_px(rB.z, gB.z, bB.z, roB.z, goB.z, boB.z);
    enhance_px(rB.w, gB.w, bB.w, roB.w, goB.w, boB.w);

    __stcs(xout,               roA);
    __stcs(xout + 256,         roB);
    __stcs(xout + HW4,         goA);
    __stcs(xout + HW4 + 256,   goB);
    __stcs(xout + 2 * HW4,     boA);
    __stcs(xout + 2 * HW4 + 256, boB);
}

extern "C" void kernel_launch(void* const* d_in, const int* in_sizes, int n_in,
                              void* d_out, int out_size) {
    const float* x = (const float*)d_in[0];
    float* out = (float*)d_out;

    int nvec    = in_sizes[0] / 12;     // 4,194,304 vec4 groups
    int blocks  = nvec / 512;           // 8192 blocks, exact cover
    cpce_kernel<<<blocks, 256>>>(x, out);
}